// round 1
// baseline (speedup 1.0000x reference)
#include <cuda_runtime.h>
#include <cstdint>
#include <cstddef>

// SBNet block-sparse 3x3 'same' conv on GB300.
// x:[4,64,448,448] f32, mask:[4,1,448,448] f32, weight:[64,64,3,3] f32, bias:[64] f32
// out:[4,64,448,448] f32 = (conv3x3_same(x, w) + bias) * block_active(14x14 blocks)
// active(by,bx) = max over 16x16 window at offset (-1,-1), stride 14, OOB skipped, > 0.5

#define Hd   448
#define Wd   448
#define Cin  64
#define Cout 64
#define NB   32      // 448/14 blocks per spatial dim
#define BST  14      // output block size
#define TIL  16      // gathered input tile (with 1px halo)
#define TROW 17      // padded smem row stride (bank-conflict-free)
#define TILE_FLOATS (Cin * TIL * TROW)       // 64*16*17 = 17408 floats
#define SMEM_BYTES  (TILE_FLOATS * 4)        // 69632 B (also covers 64*196 obuf)

// Repacked weights: [ci][tap][co], co contiguous so a channel-pair is one 64-bit load.
__device__ __align__(16) float g_WT[Cin * 9 * Cout];

__global__ void repack_kernel(const float* __restrict__ w) {
    int i = blockIdx.x * blockDim.x + threadIdx.x;
    if (i < Cout * Cin * 9) {
        int co  = i / (Cin * 9);
        int rem = i - co * (Cin * 9);
        int ci  = rem / 9;
        int tap = rem - ci * 9;
        g_WT[(ci * 9 + tap) * Cout + co] = w[i];
    }
}

// --- Blackwell packed fp32 helpers -----------------------------------------
__device__ __forceinline__ unsigned long long pack2(float v) {
    unsigned r = __float_as_uint(v);
    unsigned long long d;
    asm("mov.b64 %0, {%1, %1};" : "=l"(d) : "r"(r));
    return d;
}
__device__ __forceinline__ unsigned long long fma2(unsigned long long a,
                                                   unsigned long long b,
                                                   unsigned long long c) {
    unsigned long long d;
    asm("fma.rn.f32x2 %0, %1, %2, %3;" : "=l"(d) : "l"(a), "l"(b), "l"(c));
    return d;
}
__device__ __forceinline__ void unpack2(unsigned long long a, float& lo, float& hi) {
    unsigned l, h;
    asm("mov.b64 {%0, %1}, %2;" : "=r"(l), "=r"(h) : "l"(a));
    lo = __uint_as_float(l);
    hi = __uint_as_float(h);
}
// ---------------------------------------------------------------------------

__global__ void __launch_bounds__(256) conv_kernel(
    const float* __restrict__ x, const float* __restrict__ mask,
    const float* __restrict__ bias, float* __restrict__ out)
{
    extern __shared__ float smem[];
    __shared__ float warpmax[8];

    const int bx = blockIdx.x, by = blockIdx.y, n = blockIdx.z;
    const int tid = threadIdx.x;
    const int h0 = by * BST, w0 = bx * BST;

    // ---- Phase 0: block activity = max of mask over 16x16 gather window ----
    {
        int r = tid >> 4, c = tid & 15;
        int gy = h0 - 1 + r, gx = w0 - 1 + c;
        float mv = -1e30f;
        if ((unsigned)gy < Hd && (unsigned)gx < Wd)
            mv = mask[(size_t)n * Hd * Wd + (size_t)gy * Wd + gx];
        #pragma unroll
        for (int off = 16; off; off >>= 1)
            mv = fmaxf(mv, __shfl_xor_sync(0xffffffffu, mv, off));
        if ((tid & 31) == 0) warpmax[tid >> 5] = mv;
    }
    __syncthreads();
    float bm = warpmax[0];
    #pragma unroll
    for (int i = 1; i < 8; i++) bm = fmaxf(bm, warpmax[i]);

    if (!(bm > 0.5f)) {
        // Inactive block: write zeros (output buffer is poisoned).
        for (int i = tid; i < Cout * BST * BST; i += 256) {
            int co = i / (BST * BST);
            int p  = i - co * (BST * BST);
            int hh = p / BST, ww = p - hh * BST;
            out[((size_t)(n * Cout + co) * Hd + (h0 + hh)) * Wd + (w0 + ww)] = 0.0f;
        }
        return;
    }

    // ---- Phase 1: stage 16x16x64 halo tile into smem (zero-padded OOB) ----
    const float* xn = x + (size_t)n * Cin * Hd * Wd;
    for (int i = tid; i < Cin * 256; i += 256) {
        int ci = i >> 8, rr = (i >> 4) & 15, cc = i & 15;
        int yy = h0 - 1 + rr, xx = w0 - 1 + cc;
        float v = 0.0f;
        if ((unsigned)yy < Hd && (unsigned)xx < Wd)
            v = xn[(size_t)ci * Hd * Wd + (size_t)yy * Wd + xx];
        smem[ci * (TIL * TROW) + rr * TROW + cc] = v;
    }
    __syncthreads();

    // ---- Phase 2: compute. 256 threads = 32 cout-pairs x 8 row-groups. ----
    // Thread handles rows {g, g+8} (g>=6 -> only row g) x 14 cols x 2 couts.
    const int pair = tid >> 3;   // 0..31 -> couts (2p, 2p+1)
    const int g    = tid & 7;    // 0..7
    const bool row1ok = (g < 6);

    unsigned long long acc0[14], acc1[14];
    #pragma unroll
    for (int w = 0; w < 14; w++) { acc0[w] = 0ull; acc1[w] = 0ull; }

    const unsigned long long* wq =
        reinterpret_cast<const unsigned long long*>(g_WT) + pair;

    for (int ci = 0; ci < Cin; ci++) {
        unsigned long long wv[9];
        #pragma unroll
        for (int t = 0; t < 9; t++)
            wv[t] = wq[(ci * 9 + t) * 32];   // (ci*9+t)*64 floats + 2*pair

        const float* tb = smem + ci * (TIL * TROW);

        // output row g
        #pragma unroll
        for (int k = 0; k < 3; k++) {
            const float* rp = tb + (g + k) * TROW;
            unsigned long long xp[16];
            #pragma unroll
            for (int j = 0; j < 16; j++) xp[j] = pack2(rp[j]);
            #pragma unroll
            for (int dw = 0; dw < 3; dw++) {
                unsigned long long wk = wv[k * 3 + dw];
                #pragma unroll
                for (int w = 0; w < 14; w++)
                    acc0[w] = fma2(xp[w + dw], wk, acc0[w]);
            }
        }
        // output row g+8
        if (row1ok) {
            #pragma unroll
            for (int k = 0; k < 3; k++) {
                const float* rp = tb + (g + 8 + k) * TROW;
                unsigned long long xp[16];
                #pragma unroll
                for (int j = 0; j < 16; j++) xp[j] = pack2(rp[j]);
                #pragma unroll
                for (int dw = 0; dw < 3; dw++) {
                    unsigned long long wk = wv[k * 3 + dw];
                    #pragma unroll
                    for (int w = 0; w < 14; w++)
                        acc1[w] = fma2(xp[w + dw], wk, acc1[w]);
                }
            }
        }
    }

    __syncthreads();   // everyone done reading the tile; reuse smem as obuf

    // ---- Phase 3: stage outputs in smem [co][14][14], then coalesced STG ----
    {
        const int co0 = pair * 2;
        #pragma unroll
        for (int w = 0; w < 14; w++) {
            float lo, hi;
            unpack2(acc0[w], lo, hi);
            smem[(co0    ) * 196 + g * 14 + w] = lo;
            smem[(co0 + 1) * 196 + g * 14 + w] = hi;
        }
        if (row1ok) {
            #pragma unroll
            for (int w = 0; w < 14; w++) {
                float lo, hi;
                unpack2(acc1[w], lo, hi);
                smem[(co0    ) * 196 + (g + 8) * 14 + w] = lo;
                smem[(co0 + 1) * 196 + (g + 8) * 14 + w] = hi;
            }
        }
    }
    __syncthreads();

    for (int i = tid; i < Cout * 196; i += 256) {
        int co = i / 196;
        int p  = i - co * 196;
        int hh = p / 14, ww = p - hh * 14;
        out[((size_t)(n * Cout + co) * Hd + (h0 + hh)) * Wd + (w0 + ww)] =
            smem[i] + __ldg(&bias[co]);
    }
}

extern "C" void kernel_launch(void* const* d_in, const int* in_sizes, int n_in,
                              void* d_out, int out_size) {
    const float* x    = (const float*)d_in[0];
    const float* mask = (const float*)d_in[1];
    const float* w    = (const float*)d_in[2];
    const float* bias = (const float*)d_in[3];
    float* out = (float*)d_out;

    const int N = in_sizes[0] / (Cin * Hd * Wd);   // 4

    // Idempotent, not stream-ordered: safe during graph capture.
    cudaFuncSetAttribute(conv_kernel,
                         cudaFuncAttributeMaxDynamicSharedMemorySize, SMEM_BYTES);

    repack_kernel<<<(Cout * Cin * 9 + 255) / 256, 256>>>(w);

    dim3 grid(NB, NB, N);
    conv_kernel<<<grid, 256, SMEM_BYTES>>>(x, mask, bias, out);
}

// round 4
// speedup vs baseline: 2.9831x; 2.9831x over previous
#include <cuda_runtime.h>
#include <cstdint>
#include <cstddef>

// SBNet block-sparse 3x3 'same' conv — warp-level mma.sync TF32 implicit GEMM.
// (tcgen05 unavailable: harness PTX target is sm_103, not sm_103a.)
// x:[N,64,448,448] f32, mask:[N,1,448,448], weight:[64,64,3,3], bias:[64]
// out = (conv3x3_same(x,w)+bias) masked by 14x14-block activity.

#define Hd   448
#define Wd   448
#define HW   (Hd*Wd)
#define Cin  64
#define Cout 64
#define BST  14

// smem: Bt[64 co][580] tf32 (col = tap*64+ci), then As[64 ci][296 pos]
// (pos data at offset 17; pos index spans -17..272 incl. zeroed guards)
#define BT_STRIDE 580
#define B_FLOATS  (Cout*BT_STRIDE)        // 37120
#define B_BYTES   (B_FLOATS*4)            // 148480
#define A_STRIDE  296
#define A_FLOATS  (Cin*A_STRIDE)          // 18944
#define A_OFF_F   B_FLOATS
#define SMEM_BYTES (B_BYTES + A_FLOATS*4) // 224256

__device__ unsigned g_WB[B_FLOATS];
__device__ int      g_ctr;

static __device__ __forceinline__ uint32_t f2tf32(float f){
    uint32_t r; asm("cvt.rna.tf32.f32 %0, %1;" : "=r"(r) : "f"(f)); return r;
}
static __device__ __forceinline__ void mma_tf32(float* d, const uint32_t* a,
                                                const uint32_t* b){
    asm volatile(
        "mma.sync.aligned.m16n8k8.row.col.f32.tf32.tf32.f32 "
        "{%0,%1,%2,%3},{%4,%5,%6,%7},{%8,%9},{%0,%1,%2,%3};"
        : "+f"(d[0]), "+f"(d[1]), "+f"(d[2]), "+f"(d[3])
        : "r"(a[0]), "r"(a[1]), "r"(a[2]), "r"(a[3]), "r"(b[0]), "r"(b[1]));
}

// w[co][ci][ky][kx] -> Bt[co][tap*64+ci] (tf32). Also resets the work queue.
__global__ void repack_kernel(const float* __restrict__ w){
    int i = blockIdx.x * blockDim.x + threadIdx.x;
    if (i == 0) g_ctr = 0;
    if (i < Cout*Cin*9){
        int co  = i / (Cin*9);
        int rem = i - co*(Cin*9);
        int ci  = rem / 9;
        int tap = rem - ci*9;
        g_WB[co*BT_STRIDE + tap*64 + ci] = f2tf32(w[i]);
    }
}

__global__ void __launch_bounds__(256, 1) conv_kernel(
    const float* __restrict__ x, const float* __restrict__ mask,
    const float* __restrict__ bias, float* __restrict__ out, int total_blocks)
{
    extern __shared__ float smem[];
    float* Bt = smem;
    float* As = smem + A_OFF_F;
    __shared__ float s_wmax[8];
    __shared__ int   s_bid;
    __shared__ float s_bias[Cout];

    const int tid  = threadIdx.x;
    const int wid  = tid >> 5;
    const int lane = tid & 31;
    const int gid  = lane >> 2;   // 0..7
    const int tig  = lane & 3;    // 0..3

    // ---- one-time: copy weights to smem, zero A (incl. guards), bias ----
    {
        const uint4* src = reinterpret_cast<const uint4*>(g_WB);
        uint4* dst = reinterpret_cast<uint4*>(Bt);
        for (int j = tid; j < B_FLOATS/4; j += 256) dst[j] = src[j];
        for (int j = tid; j < A_FLOATS; j += 256) As[j] = 0.0f;
        if (tid < Cout) s_bias[tid] = bias[tid];
    }

    const int mg = wid >> 1;     // m-group 0..3  (pos base mg*64)
    const int ng = wid & 1;      // n-group 0..1  (co base ng*32)
    const int apos0 = 17 + mg*64 + gid;
    const float* brow = Bt + (ng*32 + gid) * BT_STRIDE;

    for (;;){
        if (tid == 0) s_bid = atomicAdd(&g_ctr, 1);
        __syncthreads();                       // also: prev iter smem reads done
        const int bid = s_bid;
        if (bid >= total_blocks) break;

        const int n  = bid >> 10;
        const int by = (bid >> 5) & 31;
        const int bx = bid & 31;
        const int h0 = by*BST, w0 = bx*BST;

        // ---- activity: max(mask) over 16x16 window at (h0-1, w0-1) ----
        {
            int r = tid >> 4, c = tid & 15;
            int gy = h0 - 1 + r, gx = w0 - 1 + c;
            float mv = -1e30f;
            if ((unsigned)gy < Hd && (unsigned)gx < Wd)
                mv = mask[(size_t)n*HW + (size_t)gy*Wd + gx];
            #pragma unroll
            for (int o = 16; o; o >>= 1)
                mv = fmaxf(mv, __shfl_xor_sync(0xffffffffu, mv, o));
            if (lane == 0) s_wmax[wid] = mv;
        }
        __syncthreads();
        float bm = s_wmax[0];
        #pragma unroll
        for (int i = 1; i < 8; i++) bm = fmaxf(bm, s_wmax[i]);

        if (!(bm > 0.5f)){
            for (int i = tid; i < Cout*BST; i += 256){
                int co = i / BST, r = i - co*BST;
                float2* p = reinterpret_cast<float2*>(
                    out + ((size_t)(n*Cout + co)*Hd + (h0 + r))*Wd + w0);
                #pragma unroll
                for (int j = 0; j < 7; j++) p[j] = make_float2(0.f, 0.f);
            }
            continue;
        }

        // ---- stage A: As[ci][17+pos] = tf32(x[ci][gy][gx]), pos = tid ----
        {
            const int r = tid >> 4, c = tid & 15;
            const int gy = h0 - 1 + r, gx = w0 - 1 + c;
            const bool ib = ((unsigned)gy < Hd) && ((unsigned)gx < Wd);
            const float* gp = x + (size_t)n*Cin*HW + (size_t)gy*Wd + gx;
            float* ap = As + 17 + tid;
            #pragma unroll 8
            for (int ci = 0; ci < Cin; ci++){
                float v = ib ? gp[(size_t)ci*HW] : 0.0f;
                ap[ci*A_STRIDE] = __uint_as_float(f2tf32(v));
            }
        }
        __syncthreads();

        // ---- mma: 4 mtiles x 4 ntiles per warp, K = 9 taps x 64 ci ----
        float acc[4][4][4];
        #pragma unroll
        for (int l = 0; l < 4; l++)
            #pragma unroll
            for (int t = 0; t < 4; t++)
                #pragma unroll
                for (int e = 0; e < 4; e++) acc[l][t][e] = 0.0f;

        #pragma unroll 1
        for (int tap = 0; tap < 9; tap++){
            const int dp = (tap/3 - 1)*16 + (tap%3 - 1);
            const int ar = apos0 + dp;
            #pragma unroll 2
            for (int ks = 0; ks < 8; ks++){
                const int kc = ks*8 + tig;
                uint32_t af[4][4];
                #pragma unroll
                for (int l = 0; l < 4; l++){
                    const float* p = As + kc*A_STRIDE + ar + l*16;
                    af[l][0] = __float_as_uint(p[0]);
                    af[l][1] = __float_as_uint(p[8]);
                    af[l][2] = __float_as_uint(p[4*A_STRIDE]);
                    af[l][3] = __float_as_uint(p[4*A_STRIDE + 8]);
                }
                uint32_t bf[4][2];
                const int bcol = tap*64 + ks*8 + tig;
                #pragma unroll
                for (int t = 0; t < 4; t++){
                    bf[t][0] = __float_as_uint(brow[t*8*BT_STRIDE + bcol]);
                    bf[t][1] = __float_as_uint(brow[t*8*BT_STRIDE + bcol + 4]);
                }
                #pragma unroll
                for (int l = 0; l < 4; l++)
                    #pragma unroll
                    for (int t = 0; t < 4; t++)
                        mma_tf32(acc[l][t], af[l], bf[t]);
            }
        }

        // ---- epilogue: direct STG. mt = mg*4+l is the output row. ----
        #pragma unroll
        for (int l = 0; l < 4; l++){
            const int mt = mg*4 + l;
            if (mt < 1 || mt > 14) continue;          // uniform per warp
            float* orow = out + (size_t)n*Cout*HW
                        + (size_t)(h0 + mt - 1)*Wd + (w0 - 1);
            const int c0 = gid, c1 = gid + 8;
            const bool v0 = (c0 >= 1);                // c0 <= 7 always
            const bool v1 = (c1 <= 14);
            #pragma unroll
            for (int t = 0; t < 4; t++){
                const int co = ng*32 + t*8 + 2*tig;
                const float bv0 = s_bias[co], bv1 = s_bias[co+1];
                if (v0){
                    orow[(size_t)co*HW + c0]     = acc[l][t][0] + bv0;
                    orow[(size_t)(co+1)*HW + c0] = acc[l][t][1] + bv1;
                }
                if (v1){
                    orow[(size_t)co*HW + c1]     = acc[l][t][2] + bv0;
                    orow[(size_t)(co+1)*HW + c1] = acc[l][t][3] + bv1;
                }
            }
        }
    }
}

extern "C" void kernel_launch(void* const* d_in, const int* in_sizes, int n_in,
                              void* d_out, int out_size) {
    const float* x    = (const float*)d_in[0];
    const float* mask = (const float*)d_in[1];
    const float* w    = (const float*)d_in[2];
    const float* bias = (const float*)d_in[3];
    float* out = (float*)d_out;

    const int N = in_sizes[0] / (Cin*HW);
    const int total_blocks = N * 32 * 32;

    cudaFuncSetAttribute(conv_kernel,
                         cudaFuncAttributeMaxDynamicSharedMemorySize, SMEM_BYTES);

    repack_kernel<<<(Cout*Cin*9 + 255)/256, 256>>>(w);
    conv_kernel<<<152, 256, SMEM_BYTES>>>(x, mask, bias, out, total_blocks);
}

// round 12
// speedup vs baseline: 3.1442x; 1.0540x over previous
#include <cuda_runtime.h>
#include <cstdint>
#include <cstddef>

// SBNet block-sparse 3x3 'same' conv — warp mma.sync TF32 implicit GEMM, v2.
// 512 threads (16 warps), cp.async staging with zero-fill halo.
// x:[N,64,448,448] f32, mask:[N,1,448,448], weight:[64,64,3,3], bias:[64]

#define Hd   448
#define Wd   448
#define HW   (Hd*Wd)
#define Cin  64
#define Cout 64
#define BST  14

// smem: Bt[64 co][580] tf32 (col = tap*64+ci), then As[64 ci][296 pos]
#define BT_STRIDE 580
#define B_FLOATS  (Cout*BT_STRIDE)        // 37120
#define B_BYTES   (B_FLOATS*4)            // 148480
#define A_STRIDE  296
#define A_FLOATS  (Cin*A_STRIDE)          // 18944
#define A_OFF_F   B_FLOATS
#define SMEM_BYTES (B_BYTES + A_FLOATS*4) // 224256

#define NTHREADS 512

__device__ unsigned g_WB[B_FLOATS];
__device__ int      g_ctr;

static __device__ __forceinline__ uint32_t f2tf32(float f){
    uint32_t r; asm("cvt.rna.tf32.f32 %0, %1;" : "=r"(r) : "f"(f)); return r;
}
static __device__ __forceinline__ uint32_t smem_u32(const void* p){
    uint32_t a;
    asm("{ .reg .u64 t; cvta.to.shared.u64 t, %1; cvt.u32.u64 %0, t; }"
        : "=r"(a) : "l"(p));
    return a;
}
static __device__ __forceinline__ void mma_tf32(float* d, const uint32_t* a,
                                                const uint32_t* b){
    asm volatile(
        "mma.sync.aligned.m16n8k8.row.col.f32.tf32.tf32.f32 "
        "{%0,%1,%2,%3},{%4,%5,%6,%7},{%8,%9},{%0,%1,%2,%3};"
        : "+f"(d[0]), "+f"(d[1]), "+f"(d[2]), "+f"(d[3])
        : "r"(a[0]), "r"(a[1]), "r"(a[2]), "r"(a[3]), "r"(b[0]), "r"(b[1]));
}
static __device__ __forceinline__ void cp4(uint32_t dst, const void* src, int sz){
    asm volatile("cp.async.ca.shared.global [%0], [%1], 4, %2;"
                 :: "r"(dst), "l"(src), "r"(sz) : "memory");
}
#define CP_COMMIT() asm volatile("cp.async.commit_group;" ::: "memory")
#define CP_WAIT0()  asm volatile("cp.async.wait_group 0;" ::: "memory")

// w[co][ci][ky][kx] -> Bt[co][tap*64+ci] (tf32). Also resets the work queue.
__global__ void repack_kernel(const float* __restrict__ w){
    int i = blockIdx.x * blockDim.x + threadIdx.x;
    if (i == 0) g_ctr = 0;
    if (i < Cout*Cin*9){
        int co  = i / (Cin*9);
        int rem = i - co*(Cin*9);
        int ci  = rem / 9;
        int tap = rem - ci*9;
        g_WB[co*BT_STRIDE + tap*64 + ci] = f2tf32(w[i]);
    }
}

__global__ void __launch_bounds__(NTHREADS, 1) conv_kernel(
    const float* __restrict__ x, const float* __restrict__ mask,
    const float* __restrict__ bias, float* __restrict__ out, int total_blocks)
{
    extern __shared__ float smem[];
    float* Bt = smem;
    float* As = smem + A_OFF_F;
    __shared__ float s_wmax[8];
    __shared__ int   s_bid;
    __shared__ float s_bias[Cout];

    const int tid  = threadIdx.x;
    const int wid  = tid >> 5;
    const int lane = tid & 31;
    const int gid  = lane >> 2;   // 0..7
    const int tig  = lane & 3;    // 0..3

    // ---- one-time: weights -> smem, zero A (incl. guards), bias ----
    {
        const uint4* src = reinterpret_cast<const uint4*>(g_WB);
        uint4* dst = reinterpret_cast<uint4*>(Bt);
        for (int j = tid; j < B_FLOATS/4; j += NTHREADS) dst[j] = src[j];
        for (int j = tid; j < A_FLOATS; j += NTHREADS) As[j] = 0.0f;
        if (tid < Cout) s_bias[tid] = bias[tid];
    }

    const int mg = wid >> 1;     // 0..7   (pos base mg*32)
    const int ng = wid & 1;      // 0..1   (co base ng*32)
    const int apos0 = 17 + mg*32 + gid;
    const float* brow = Bt + (ng*32 + gid) * BT_STRIDE;

    // staging identity: 2 halves of 512 threads cover pos 0..255 x ci-slabs
    const int sp    = tid & 255;           // position 0..255
    const int shalf = tid >> 8;            // ci slab: 0 -> ci 0..31, 1 -> 32..63
    const int sr = sp >> 4, sc = sp & 15;
    const uint32_t a_dst = smem_u32(As + shalf*32*A_STRIDE + 17 + sp);

    for (;;){
        if (tid == 0) s_bid = atomicAdd(&g_ctr, 1);
        __syncthreads();
        const int bid = s_bid;
        if (bid >= total_blocks) break;

        const int n  = bid >> 10;
        const int by = (bid >> 5) & 31;
        const int bx = bid & 31;
        const int h0 = by*BST, w0 = bx*BST;

        // ---- activity: max(mask) over 16x16 window at (h0-1, w0-1) ----
        if (tid < 256){
            int gy = h0 - 1 + sr, gx = w0 - 1 + sc;
            float mv = -1e30f;
            if ((unsigned)gy < Hd && (unsigned)gx < Wd)
                mv = mask[(size_t)n*HW + (size_t)gy*Wd + gx];
            #pragma unroll
            for (int o = 16; o; o >>= 1)
                mv = fmaxf(mv, __shfl_xor_sync(0xffffffffu, mv, o));
            if (lane == 0) s_wmax[wid] = mv;
        }
        __syncthreads();
        float bm = s_wmax[0];
        #pragma unroll
        for (int i = 1; i < 8; i++) bm = fmaxf(bm, s_wmax[i]);

        if (!(bm > 0.5f)){
            for (int i = tid; i < Cout*BST; i += NTHREADS){
                int co = i / BST, r = i - co*BST;
                float2* p = reinterpret_cast<float2*>(
                    out + ((size_t)(n*Cout + co)*Hd + (h0 + r))*Wd + w0);
                #pragma unroll
                for (int j = 0; j < 7; j++) p[j] = make_float2(0.f, 0.f);
            }
            continue;
        }

        // ---- stage A via cp.async (zero-fill OOB). Raw f32; HW tf32-truncates. ----
        {
            const int gy = h0 - 1 + sr, gx = w0 - 1 + sc;
            const bool ib = ((unsigned)gy < Hd) && ((unsigned)gx < Wd);
            const float* gp = ib
                ? (x + (size_t)n*Cin*HW + (size_t)(shalf*32)*HW + (size_t)gy*Wd + gx)
                : x;
            const int sz = ib ? 4 : 0;
            #pragma unroll
            for (int ci = 0; ci < 32; ci++)
                cp4(a_dst + ci*(A_STRIDE*4), gp + (size_t)ci*HW, sz);
            CP_COMMIT();
            CP_WAIT0();
        }
        __syncthreads();

        // ---- mma: 2 mtiles x 4 ntiles per warp, K = 9 taps x 64 ci ----
        float acc[2][4][4];
        #pragma unroll
        for (int l = 0; l < 2; l++)
            #pragma unroll
            for (int t = 0; t < 4; t++)
                #pragma unroll
                for (int e = 0; e < 4; e++) acc[l][t][e] = 0.0f;

        #pragma unroll 1
        for (int tap = 0; tap < 9; tap++){
            const int dp = (tap/3 - 1)*16 + (tap%3 - 1);
            const int ar = apos0 + dp;
            #pragma unroll 4
            for (int ks = 0; ks < 8; ks++){
                const int kc = ks*8 + tig;
                uint32_t af[2][4];
                #pragma unroll
                for (int l = 0; l < 2; l++){
                    const float* p = As + kc*A_STRIDE + ar + l*16;
                    af[l][0] = __float_as_uint(p[0]);
                    af[l][1] = __float_as_uint(p[8]);
                    af[l][2] = __float_as_uint(p[4*A_STRIDE]);
                    af[l][3] = __float_as_uint(p[4*A_STRIDE + 8]);
                }
                uint32_t bf[4][2];
                const int bcol = tap*64 + ks*8 + tig;
                #pragma unroll
                for (int t = 0; t < 4; t++){
                    bf[t][0] = __float_as_uint(brow[t*8*BT_STRIDE + bcol]);
                    bf[t][1] = __float_as_uint(brow[t*8*BT_STRIDE + bcol + 4]);
                }
                #pragma unroll
                for (int l = 0; l < 2; l++)
                    #pragma unroll
                    for (int t = 0; t < 4; t++)
                        mma_tf32(acc[l][t], af[l], bf[t]);
            }
        }

        // ---- epilogue: direct STG. mt = mg*2+l is the output row index. ----
        #pragma unroll
        for (int l = 0; l < 2; l++){
            const int mt = mg*2 + l;
            if (mt < 1 || mt > 14) continue;          // uniform per warp
            float* orow = out + (size_t)n*Cout*HW
                        + (size_t)(h0 + mt - 1)*Wd + (w0 - 1);
            const int c0 = gid, c1 = gid + 8;
            const bool v0 = (c0 >= 1);
            const bool v1 = (c1 <= 14);
            #pragma unroll
            for (int t = 0; t < 4; t++){
                const int co = ng*32 + t*8 + 2*tig;
                const float bv0 = s_bias[co], bv1 = s_bias[co+1];
                if (v0){
                    orow[(size_t)co*HW + c0]     = acc[l][t][0] + bv0;
                    orow[(size_t)(co+1)*HW + c0] = acc[l][t][1] + bv1;
                }
                if (v1){
                    orow[(size_t)co*HW + c1]     = acc[l][t][2] + bv0;
                    orow[(size_t)(co+1)*HW + c1] = acc[l][t][3] + bv1;
                }
            }
        }
    }
}

extern "C" void kernel_launch(void* const* d_in, const int* in_sizes, int n_in,
                              void* d_out, int out_size) {
    const float* x    = (const float*)d_in[0];
    const float* mask = (const float*)d_in[1];
    const float* w    = (const float*)d_in[2];
    const float* bias = (const float*)d_in[3];
    float* out = (float*)d_out;

    const int N = in_sizes[0] / (Cin*HW);
    const int total_blocks = N * 32 * 32;

    cudaFuncSetAttribute(conv_kernel,
                         cudaFuncAttributeMaxDynamicSharedMemorySize, SMEM_BYTES);

    repack_kernel<<<(Cout*Cin*9 + 255)/256, 256>>>(w);
    conv_kernel<<<152, NTHREADS, SMEM_BYTES>>>(x, mask, bias, out, total_blocks);
}